// round 2
// baseline (speedup 1.0000x reference)
#include <cuda_runtime.h>
#include <cstdint>
#include <cstddef>

#define B_  256
#define L_  2048
#define H_  128
#define H2_ 256
#define V_  32000
#define TB  64        // tokens per encode block

// ---------------- scratch (static device globals; no allocs allowed) ----------------
__device__ float g_h[(size_t)B_ * L_ * H_];   // encoded h_all [B,L,H]  (256 MB)
__device__ float g_r[B_ * H_];                // r  = M_fin @ h_last
__device__ float g_r2[B_ * H_];               // r2 = r @ Wrp + brp

// =====================================================================
// Kernel 1: fused encode.  Per block: 64 tokens.
//   e = embed[seq]; u = relu(e@W1+b1); y = u@W2 + b2 + e; h = LN(y)*gamma+beta
// =====================================================================
__global__ void __launch_bounds__(256, 1) encode_kernel(
    const int*   __restrict__ seq,   const float* __restrict__ embed,
    const float* __restrict__ W1,    const float* __restrict__ b1,
    const float* __restrict__ W2,    const float* __restrict__ b2,
    const float* __restrict__ gamma, const float* __restrict__ beta)
{
    extern __shared__ float sm[];
    float* Es = sm;               // [64][132]  e tile (padded)
    float* Us = Es + 64 * 132;    // [64][260]  u tile (padded); reused as y [64][132]
    float* Ws = Us + 64 * 260;    // weight chunk, up to [32][256]

    const int tid = threadIdx.x;
    const int ty  = tid >> 4;     // 0..15
    const int tx  = tid & 15;     // 0..15
    const int tok0 = blockIdx.x * TB;

    // ---- gather embeddings ----
    for (int i = tid; i < TB * H_; i += 256) {
        int row = i >> 7, col = i & 127;
        int s = seq[tok0 + row];
        Es[row * 132 + col] = embed[(size_t)s * H_ + col];
    }

    // ---- GEMM1: u = relu(e @ W1 + b1)   (64x256, K=128) ----
    float acc[4][16];
    #pragma unroll
    for (int r = 0; r < 4; r++)
        #pragma unroll
        for (int j = 0; j < 16; j++) acc[r][j] = 0.f;

    for (int kc = 0; kc < H_; kc += 32) {
        __syncthreads();
        for (int i = tid; i < 32 * H2_; i += 256) {
            int rr = i >> 8, cc = i & 255;
            Ws[i] = W1[(kc + rr) * H2_ + cc];
        }
        __syncthreads();
        #pragma unroll 8
        for (int kk = 0; kk < 32; kk++) {
            float a[4], bb[16];
            #pragma unroll
            for (int r = 0; r < 4; r++) a[r] = Es[(ty * 4 + r) * 132 + kc + kk];
            #pragma unroll
            for (int j = 0; j < 16; j++) bb[j] = Ws[kk * H2_ + tx + 16 * j];
            #pragma unroll
            for (int r = 0; r < 4; r++)
                #pragma unroll
                for (int j = 0; j < 16; j++) acc[r][j] = fmaf(a[r], bb[j], acc[r][j]);
        }
    }
    __syncthreads();
    #pragma unroll
    for (int r = 0; r < 4; r++)
        #pragma unroll
        for (int j = 0; j < 16; j++) {
            int col = tx + 16 * j;
            Us[(ty * 4 + r) * 260 + col] = fmaxf(acc[r][j] + b1[col], 0.f);
        }

    // ---- GEMM2: y = u @ W2 + b2 + e   (64x128, K=256) ----
    float acc2[4][8];
    #pragma unroll
    for (int r = 0; r < 4; r++)
        #pragma unroll
        for (int j = 0; j < 8; j++) acc2[r][j] = 0.f;

    for (int kc = 0; kc < H2_; kc += 32) {
        __syncthreads();
        for (int i = tid; i < 32 * H_; i += 256) {
            int rr = i >> 7, cc = i & 127;
            Ws[i] = W2[(kc + rr) * H_ + cc];
        }
        __syncthreads();
        #pragma unroll 8
        for (int kk = 0; kk < 32; kk++) {
            float a[4], bb[8];
            #pragma unroll
            for (int r = 0; r < 4; r++) a[r] = Us[(ty * 4 + r) * 260 + kc + kk];
            #pragma unroll
            for (int j = 0; j < 8; j++) bb[j] = Ws[kk * H_ + tx + 16 * j];
            #pragma unroll
            for (int r = 0; r < 4; r++)
                #pragma unroll
                for (int j = 0; j < 8; j++) acc2[r][j] = fmaf(a[r], bb[j], acc2[r][j]);
        }
    }
    __syncthreads();   // all Us (u) reads done before overwriting with y
    #pragma unroll
    for (int r = 0; r < 4; r++)
        #pragma unroll
        for (int j = 0; j < 8; j++) {
            int row = ty * 4 + r, col = tx + 16 * j;
            Us[row * 132 + col] = acc2[r][j] + b2[col] + Es[row * 132 + col];
        }
    __syncthreads();

    // ---- LayerNorm: 8 warps x 8 rows ----
    const int wid = tid >> 5, lane = tid & 31;
    #pragma unroll
    for (int rr = 0; rr < 8; rr++) {
        int row = wid * 8 + rr;
        float v[4];
        #pragma unroll
        for (int q = 0; q < 4; q++) v[q] = Us[row * 132 + lane + 32 * q];
        float s = v[0] + v[1] + v[2] + v[3];
        #pragma unroll
        for (int o = 16; o; o >>= 1) s += __shfl_xor_sync(0xffffffffu, s, o);
        float mu = s * (1.f / 128.f);
        float d[4], sq = 0.f;
        #pragma unroll
        for (int q = 0; q < 4; q++) { d[q] = v[q] - mu; sq = fmaf(d[q], d[q], sq); }
        #pragma unroll
        for (int o = 16; o; o >>= 1) sq += __shfl_xor_sync(0xffffffffu, sq, o);
        float inv = rsqrtf(sq * (1.f / 128.f) + 1e-5f);
        size_t base = (size_t)(tok0 + row) * H_;
        #pragma unroll
        for (int q = 0; q < 4; q++) {
            int col = lane + 32 * q;
            g_h[base + col] = d[q] * inv * gamma[col] + beta[col];
        }
    }
}

// =====================================================================
// Kernel 2: energy-gated delta scan. One CTA per batch, M in registers.
// Thread (ty,tx) on 16x16 grid owns M[ty*8 .. ty*8+7][tx*8 .. tx*8+7].
// =====================================================================
__global__ void __launch_bounds__(256, 2) scan_kernel()
{
    __shared__ float k_s[128];
    __shared__ float err_s[128];
    __shared__ float vp_part[128][17];
    __shared__ float red[8];

    const int b   = blockIdx.x;
    const int tid = threadIdx.x;
    const int ty  = tid >> 4, tx = tid & 15;
    const float* __restrict__ hb = g_h + (size_t)b * L_ * H_;

    float M[8][8];
    #pragma unroll
    for (int r = 0; r < 8; r++)
        #pragma unroll
        for (int c = 0; c < 8; c++) M[r][c] = 0.f;

    float knext = 0.f;
    if (tid < 128) knext = hb[tid];

    for (int t = 0; t < L_; t++) {
        __syncthreads();                      // all consumers of previous k/err/red done
        if (tid < 128) {
            float kv = knext;
            k_s[tid] = kv;
            float p = kv * kv;
            #pragma unroll
            for (int o = 16; o; o >>= 1) p += __shfl_xor_sync(0xffffffffu, p, o);
            if ((tid & 31) == 0) red[tid >> 5] = p;
            if (t + 1 < L_) knext = hb[(size_t)(t + 1) * H_ + tid];   // prefetch
        }
        __syncthreads();

        // partial matvec: vp_part[i][tx] = sum over this thread's 8 cols
        float kreg[8];
        #pragma unroll
        for (int c = 0; c < 8; c++) kreg[c] = k_s[tx * 8 + c];
        #pragma unroll
        for (int r = 0; r < 8; r++) {
            float s = 0.f;
            #pragma unroll
            for (int c = 0; c < 8; c++) s = fmaf(M[r][c], kreg[c], s);
            vp_part[ty * 8 + r][tx] = s;
        }
        __syncthreads();

        if (tid < 128) {
            float vp = 0.f;
            #pragma unroll
            for (int x = 0; x < 16; x++) vp += vp_part[tid][x];
            float kk = red[0] + red[1] + red[2] + red[3];
            if (t == L_ - 1) {
                g_r[b * H_ + tid] = vp;       // r = M_fin @ h_last
            } else {
                float e = k_s[tid] - vp / (kk + 1e-6f);
                err_s[tid] = e;
                float p = e * e;
                #pragma unroll
                for (int o = 16; o; o >>= 1) p += __shfl_xor_sync(0xffffffffu, p, o);
                if ((tid & 31) == 0) red[4 + (tid >> 5)] = p;
            }
        }
        __syncthreads();

        if (t < L_ - 1) {
            float e2 = red[4] + red[5] + red[6] + red[7];
            float kk = red[0] + red[1] + red[2] + red[3];
            if (sqrtf(e2) > 0.4f * sqrtf(kk)) {      // gate (uniform per CTA)
                float er[8];
                #pragma unroll
                for (int r = 0; r < 8; r++) er[r] = err_s[ty * 8 + r];
                #pragma unroll
                for (int r = 0; r < 8; r++)
                    #pragma unroll
                    for (int c = 0; c < 8; c++) M[r][c] = fmaf(er[r], kreg[c], M[r][c]);
            }
        }
    }
}

// =====================================================================
// Kernel 3: r2 = r @ Wrp + brp   (256x128 @ 128x128)
// =====================================================================
__global__ void __launch_bounds__(256, 1) rproj_kernel(
    const float* __restrict__ Wrp, const float* __restrict__ brp)
{
    extern __shared__ float sm[];
    float* Rs = sm;               // [64][132]
    float* Ws = sm + 64 * 132;    // [128][128]
    const int tid = threadIdx.x, ty = tid >> 4, tx = tid & 15;
    const int m0 = blockIdx.x * 64;

    for (int i = tid; i < 64 * 128; i += 256) {
        int row = i >> 7, col = i & 127;
        Rs[row * 132 + col] = g_r[(m0 + row) * H_ + col];
    }
    for (int i = tid; i < 128 * 128; i += 256) Ws[i] = Wrp[i];
    __syncthreads();

    float acc[4][8];
    #pragma unroll
    for (int r = 0; r < 4; r++)
        #pragma unroll
        for (int j = 0; j < 8; j++) acc[r][j] = 0.f;
    #pragma unroll 8
    for (int k = 0; k < 128; k++) {
        float a[4], bb[8];
        #pragma unroll
        for (int r = 0; r < 4; r++) a[r] = Rs[(ty * 4 + r) * 132 + k];
        #pragma unroll
        for (int j = 0; j < 8; j++) bb[j] = Ws[k * 128 + tx + 16 * j];
        #pragma unroll
        for (int r = 0; r < 4; r++)
            #pragma unroll
            for (int j = 0; j < 8; j++) acc[r][j] = fmaf(a[r], bb[j], acc[r][j]);
    }
    #pragma unroll
    for (int r = 0; r < 4; r++)
        #pragma unroll
        for (int j = 0; j < 8; j++) {
            int row = m0 + ty * 4 + r, col = tx + 16 * j;
            g_r2[row * H_ + col] = acc[r][j] + brp[col];
        }
}

// =====================================================================
// Kernel 4: out = r2 @ Wout + bout   (256x128 @ 128x32000)
// =====================================================================
__global__ void __launch_bounds__(256, 1) out_kernel(
    const float* __restrict__ Wout, const float* __restrict__ bout,
    float* __restrict__ out)
{
    extern __shared__ float sm[];
    float* Rs = sm;               // [64][132]
    float* Ws = sm + 64 * 132;    // [128][128] chunk of Wout
    const int tid = threadIdx.x, ty = tid >> 4, tx = tid & 15;
    const int n0 = blockIdx.x * 128;
    const int m0 = blockIdx.y * 64;

    for (int i = tid; i < 64 * 128; i += 256) {
        int row = i >> 7, col = i & 127;
        Rs[row * 132 + col] = g_r2[(m0 + row) * H_ + col];
    }
    for (int i = tid; i < 128 * 128; i += 256) {
        int k = i >> 7, c = i & 127;
        Ws[i] = Wout[(size_t)k * V_ + n0 + c];
    }
    __syncthreads();

    float acc[4][8];
    #pragma unroll
    for (int r = 0; r < 4; r++)
        #pragma unroll
        for (int j = 0; j < 8; j++) acc[r][j] = 0.f;
    #pragma unroll 8
    for (int k = 0; k < 128; k++) {
        float a[4], bb[8];
        #pragma unroll
        for (int r = 0; r < 4; r++) a[r] = Rs[(ty * 4 + r) * 132 + k];
        #pragma unroll
        for (int j = 0; j < 8; j++) bb[j] = Ws[k * 128 + tx + 16 * j];
        #pragma unroll
        for (int r = 0; r < 4; r++)
            #pragma unroll
            for (int j = 0; j < 8; j++) acc[r][j] = fmaf(a[r], bb[j], acc[r][j]);
    }
    #pragma unroll
    for (int r = 0; r < 4; r++)
        #pragma unroll
        for (int j = 0; j < 8; j++) {
            int row = m0 + ty * 4 + r, col = n0 + tx + 16 * j;
            out[(size_t)row * V_ + col] = acc[r][j] + bout[col];
        }
}

// =====================================================================
// launcher
// =====================================================================
extern "C" void kernel_launch(void* const* d_in, const int* in_sizes, int n_in,
                              void* d_out, int out_size)
{
    const int*   seq   = (const int*)  d_in[0];
    const float* embed = (const float*)d_in[1];
    const float* W1    = (const float*)d_in[2];
    const float* b1    = (const float*)d_in[3];
    const float* W2    = (const float*)d_in[4];
    const float* b2    = (const float*)d_in[5];
    const float* gamma = (const float*)d_in[6];
    const float* beta  = (const float*)d_in[7];
    const float* Wrp   = (const float*)d_in[8];
    const float* brp   = (const float*)d_in[9];
    const float* Wout  = (const float*)d_in[10];
    const float* bout  = (const float*)d_in[11];
    float* out = (float*)d_out;

    const int ENC_SMEM  = (64 * 132 + 64 * 260 + 32 * 256) * 4;   // 133120 B
    const int PROJ_SMEM = (64 * 132 + 128 * 128) * 4;             //  99328 B

    cudaFuncSetAttribute(encode_kernel, cudaFuncAttributeMaxDynamicSharedMemorySize, ENC_SMEM);
    cudaFuncSetAttribute(rproj_kernel,  cudaFuncAttributeMaxDynamicSharedMemorySize, PROJ_SMEM);
    cudaFuncSetAttribute(out_kernel,    cudaFuncAttributeMaxDynamicSharedMemorySize, PROJ_SMEM);

    encode_kernel<<<(B_ * L_) / TB, 256, ENC_SMEM>>>(seq, embed, W1, b1, W2, b2, gamma, beta);
    scan_kernel<<<B_, 256>>>();
    rproj_kernel<<<B_ / 64, 256, PROJ_SMEM>>>(Wrp, brp);
    out_kernel<<<dim3(V_ / 128, B_ / 64), 256, PROJ_SMEM>>>(Wout, bout, out);
}

// round 4
// speedup vs baseline: 1.0110x; 1.0110x over previous
#include <cuda_runtime.h>
#include <cstdint>
#include <cstddef>

#define B_  256
#define L_  2048
#define H_  128
#define H2_ 256
#define V_  32000

// ---------------- scratch (static device globals; no allocs allowed) ----------------
__device__ float g_h[(size_t)B_ * L_ * H_];   // encoded h_all [B,L,H]
__device__ float g_r[B_ * H_];
__device__ float g_r2[B_ * H_];

// ============================ mma helpers (baseline PTX, no 'a' features) ============================
__device__ __forceinline__ uint32_t f2tf32(float x) {
    uint32_t r;
    asm("cvt.rna.tf32.f32 %0, %1;" : "=r"(r) : "f"(x));
    return r;
}
__device__ __forceinline__ void mma_tf32(float* c, const uint32_t* a, const uint32_t* b) {
    asm volatile("mma.sync.aligned.m16n8k8.row.col.f32.tf32.tf32.f32 "
        "{%0,%1,%2,%3}, {%4,%5,%6,%7}, {%8,%9}, {%0,%1,%2,%3};"
        : "+f"(c[0]), "+f"(c[1]), "+f"(c[2]), "+f"(c[3])
        : "r"(a[0]), "r"(a[1]), "r"(a[2]), "r"(a[3]), "r"(b[0]), "r"(b[1]));
}
// derive (h, m) tf32 split of f32 x:  x = h + m + O(2^-22 x)
__device__ __forceinline__ void tsplit(float x, uint32_t& h, uint32_t& m) {
    h = f2tf32(x);
    m = f2tf32(x - __uint_as_float(h));
}

// =====================================================================
// Encode kernel: 64 tokens/CTA, 256 threads (8 warps).
//   GEMM1: u = relu(e @ W1 + b1)      [64,256] = [64,128] @ [128,256]
//   GEMM2: y = u @ W2 + b2 + e        [64,128] = [64,256] @ [256,128]
//   LayerNorm(y) -> g_h
// tf32 mma with 4-pass (hh,hm,mh,mm) split; operands stored f32 in SMEM,
// splits derived in registers at load.
// =====================================================================
#define EPAD 132       // 132 % 32 == 4  -> conflict-free fragment loads
#define UPAD 260       // 260 % 32 == 4
#define WPAD1 132
#define WPAD2 68       // 68 % 32 == 4
#define OFF_E 0
#define OFF_U (64 * EPAD)
#define OFF_W (64 * EPAD + 64 * UPAD)
#define ENC_FLOATS (64 * EPAD + 64 * UPAD + 128 * WPAD2)
#define ENC_SMEM (ENC_FLOATS * 4)       // 135168 B

__global__ void __launch_bounds__(256, 1) encode_mma(
    const int*   __restrict__ seq,   const float* __restrict__ embed,
    const float* __restrict__ W1,    const float* __restrict__ b1,
    const float* __restrict__ W2,    const float* __restrict__ b2,
    const float* __restrict__ gamma, const float* __restrict__ beta)
{
    extern __shared__ float sm[];
    float* eBuf = sm + OFF_E;    // [64][132]  e (f32, exact — used for residual too)
    float* uBuf = sm + OFF_U;    // [64][260]  u (f32)
    float* wBuf = sm + OFF_W;    // weight chunk, max 128*68 floats

    const int tid  = threadIdx.x;
    const int w    = tid >> 5, lane = tid & 31;
    const int wy   = w >> 1,   wx   = w & 1;       // warp grid 4x2
    const int gr   = lane >> 2, gc  = lane & 3;    // quad row/col
    const int tok0 = blockIdx.x * 64;

    // ---- gather embeddings (f32) ----
    for (int i = tid; i < 64 * 128; i += 256) {
        int row = i >> 7, col = i & 127;
        int s = seq[tok0 + row];
        eBuf[row * EPAD + col] = embed[(size_t)s * 128 + col];
    }

    const int ar0 = (wy * 16 + gr) * EPAD;         // A row bases (GEMM1)
    const int ar1 = (wy * 16 + gr + 8) * EPAD;

    // ---------------- GEMM1: 4 N-chunks of 64 ----------------
    for (int c = 0; c < 4; c++) {
        __syncthreads();                            // wBuf free / eBuf ready (c==0)
        for (int i = tid; i < 64 * 128; i += 256) { // wBuf[n][k] = W1[k][64c+n]
            int n = i & 63, k = i >> 6;
            wBuf[n * WPAD1 + k] = W1[k * H2_ + 64 * c + n];
        }
        __syncthreads();

        float acc[4][4];
        #pragma unroll
        for (int nf = 0; nf < 4; nf++)
            #pragma unroll
            for (int j = 0; j < 4; j++) acc[nf][j] = 0.f;

        #pragma unroll 4
        for (int ks = 0; ks < 16; ks++) {
            int k0 = ks * 8;
            uint32_t ah[4], am[4];
            tsplit(eBuf[ar0 + k0 + gc],     ah[0], am[0]);
            tsplit(eBuf[ar1 + k0 + gc],     ah[1], am[1]);
            tsplit(eBuf[ar0 + k0 + 4 + gc], ah[2], am[2]);
            tsplit(eBuf[ar1 + k0 + 4 + gc], ah[3], am[3]);
            #pragma unroll
            for (int nf = 0; nf < 4; nf++) {
                int n = wx * 32 + nf * 8 + gr;
                uint32_t bh[2], bm[2];
                tsplit(wBuf[n * WPAD1 + k0 + gc],     bh[0], bm[0]);
                tsplit(wBuf[n * WPAD1 + k0 + 4 + gc], bh[1], bm[1]);
                mma_tf32(acc[nf], ah, bh);
                mma_tf32(acc[nf], ah, bm);
                mma_tf32(acc[nf], am, bh);
                mma_tf32(acc[nf], am, bm);
            }
        }
        // u = relu(acc + b1) -> uBuf (f32)
        #pragma unroll
        for (int nf = 0; nf < 4; nf++)
            #pragma unroll
            for (int j = 0; j < 4; j++) {
                int row = wy * 16 + gr + ((j >> 1) ? 8 : 0);
                int col = 64 * c + wx * 32 + nf * 8 + gc * 2 + (j & 1);
                uBuf[row * UPAD + col] = fmaxf(acc[nf][j] + __ldg(b1 + col), 0.f);
            }
    }

    // ---------------- GEMM2: 4 K-chunks of 64 ----------------
    float acc2[8][4];
    #pragma unroll
    for (int nf = 0; nf < 8; nf++)
        #pragma unroll
        for (int j = 0; j < 4; j++) acc2[nf][j] = 0.f;

    const int ur0 = (wy * 16 + gr) * UPAD;
    const int ur1 = (wy * 16 + gr + 8) * UPAD;

    for (int c2 = 0; c2 < 4; c2++) {
        __syncthreads();                            // all wBuf / uBuf consumers done
        for (int i = tid; i < 128 * 64; i += 256) { // wBuf[n][kk] = W2[64c2+kk][n]
            int n = i & 127, kk = i >> 7;
            wBuf[n * WPAD2 + kk] = W2[(64 * c2 + kk) * H_ + n];
        }
        __syncthreads();

        #pragma unroll 4
        for (int ks = 0; ks < 8; ks++) {
            int kg = 64 * c2 + ks * 8;              // global k into uBuf
            int kl = ks * 8;                        // local k into wBuf
            uint32_t ah[4], am[4];
            tsplit(uBuf[ur0 + kg + gc],     ah[0], am[0]);
            tsplit(uBuf[ur1 + kg + gc],     ah[1], am[1]);
            tsplit(uBuf[ur0 + kg + 4 + gc], ah[2], am[2]);
            tsplit(uBuf[ur1 + kg + 4 + gc], ah[3], am[3]);
            #pragma unroll
            for (int nf = 0; nf < 8; nf++) {
                int n = wx * 64 + nf * 8 + gr;
                uint32_t bh[2], bm[2];
                tsplit(wBuf[n * WPAD2 + kl + gc],     bh[0], bm[0]);
                tsplit(wBuf[n * WPAD2 + kl + 4 + gc], bh[1], bm[1]);
                mma_tf32(acc2[nf], ah, bh);
                mma_tf32(acc2[nf], ah, bm);
                mma_tf32(acc2[nf], am, bh);
                mma_tf32(acc2[nf], am, bm);
            }
        }
    }

    // ---------------- epilogue: y = acc2 + b2 + e ; LayerNorm ----------------
    __syncthreads();                 // wBuf reads done -> reuse as yBuf
    float* yBuf = wBuf;              // [64][132] f32 (8448 <= 8704 floats)
    #pragma unroll
    for (int nf = 0; nf < 8; nf++)
        #pragma unroll
        for (int j = 0; j < 4; j++) {
            int row = wy * 16 + gr + ((j >> 1) ? 8 : 0);
            int col = wx * 64 + nf * 8 + gc * 2 + (j & 1);
            yBuf[row * EPAD + col] = acc2[nf][j] + __ldg(b2 + col) + eBuf[row * EPAD + col];
        }
    __syncthreads();

    // LayerNorm: 8 warps x 8 rows
    #pragma unroll
    for (int rr = 0; rr < 8; rr++) {
        int row = w * 8 + rr;
        float v[4];
        #pragma unroll
        for (int q = 0; q < 4; q++) v[q] = yBuf[row * EPAD + lane + 32 * q];
        float s = v[0] + v[1] + v[2] + v[3];
        #pragma unroll
        for (int o = 16; o; o >>= 1) s += __shfl_xor_sync(0xffffffffu, s, o);
        float mu = s * (1.f / 128.f);
        float d[4], sq = 0.f;
        #pragma unroll
        for (int q = 0; q < 4; q++) { d[q] = v[q] - mu; sq = fmaf(d[q], d[q], sq); }
        #pragma unroll
        for (int o = 16; o; o >>= 1) sq += __shfl_xor_sync(0xffffffffu, sq, o);
        float inv = rsqrtf(sq * (1.f / 128.f) + 1e-5f);
        size_t base = (size_t)(tok0 + row) * H_;
        #pragma unroll
        for (int q = 0; q < 4; q++) {
            int col = lane + 32 * q;
            g_h[base + col] = d[q] * inv * __ldg(gamma + col) + __ldg(beta + col);
        }
    }
}

// =====================================================================
// Kernel 2: energy-gated delta scan (unchanged — passed R1/R2)
// =====================================================================
__global__ void __launch_bounds__(256, 2) scan_kernel()
{
    __shared__ float k_s[128];
    __shared__ float err_s[128];
    __shared__ float vp_part[128][17];
    __shared__ float red[8];

    const int b   = blockIdx.x;
    const int tid = threadIdx.x;
    const int ty  = tid >> 4, tx = tid & 15;
    const float* __restrict__ hb = g_h + (size_t)b * L_ * H_;

    float M[8][8];
    #pragma unroll
    for (int r = 0; r < 8; r++)
        #pragma unroll
        for (int c = 0; c < 8; c++) M[r][c] = 0.f;

    float knext = 0.f;
    if (tid < 128) knext = hb[tid];

    for (int t = 0; t < L_; t++) {
        __syncthreads();
        if (tid < 128) {
            float kv = knext;
            k_s[tid] = kv;
            float p = kv * kv;
            #pragma unroll
            for (int o = 16; o; o >>= 1) p += __shfl_xor_sync(0xffffffffu, p, o);
            if ((tid & 31) == 0) red[tid >> 5] = p;
            if (t + 1 < L_) knext = hb[(size_t)(t + 1) * H_ + tid];
        }
        __syncthreads();

        float kreg[8];
        #pragma unroll
        for (int c = 0; c < 8; c++) kreg[c] = k_s[tx * 8 + c];
        #pragma unroll
        for (int r = 0; r < 8; r++) {
            float s = 0.f;
            #pragma unroll
            for (int c = 0; c < 8; c++) s = fmaf(M[r][c], kreg[c], s);
            vp_part[ty * 8 + r][tx] = s;
        }
        __syncthreads();

        if (tid < 128) {
            float vp = 0.f;
            #pragma unroll
            for (int x = 0; x < 16; x++) vp += vp_part[tid][x];
            float kk = red[0] + red[1] + red[2] + red[3];
            if (t == L_ - 1) {
                g_r[b * H_ + tid] = vp;
            } else {
                float e = k_s[tid] - vp / (kk + 1e-6f);
                err_s[tid] = e;
                float p = e * e;
                #pragma unroll
                for (int o = 16; o; o >>= 1) p += __shfl_xor_sync(0xffffffffu, p, o);
                if ((tid & 31) == 0) red[4 + (tid >> 5)] = p;
            }
        }
        __syncthreads();

        if (t < L_ - 1) {
            float e2 = red[4] + red[5] + red[6] + red[7];
            float kk = red[0] + red[1] + red[2] + red[3];
            if (sqrtf(e2) > 0.4f * sqrtf(kk)) {
                float er[8];
                #pragma unroll
                for (int r = 0; r < 8; r++) er[r] = err_s[ty * 8 + r];
                #pragma unroll
                for (int r = 0; r < 8; r++)
                    #pragma unroll
                    for (int c = 0; c < 8; c++) M[r][c] = fmaf(er[r], kreg[c], M[r][c]);
            }
        }
    }
}

// =====================================================================
// Kernel 3: r2 = r @ Wrp + brp
// =====================================================================
__global__ void __launch_bounds__(256, 1) rproj_kernel(
    const float* __restrict__ Wrp, const float* __restrict__ brp)
{
    extern __shared__ float smf[];
    float* Rs = smf;
    float* Ws = smf + 64 * 132;
    const int tid = threadIdx.x, ty = tid >> 4, tx = tid & 15;
    const int m0 = blockIdx.x * 64;

    for (int i = tid; i < 64 * 128; i += 256) {
        int r = i >> 7, c = i & 127;
        Rs[r * 132 + c] = g_r[(m0 + r) * H_ + c];
    }
    for (int i = tid; i < 128 * 128; i += 256) Ws[i] = Wrp[i];
    __syncthreads();

    float acc[4][8];
    #pragma unroll
    for (int r = 0; r < 4; r++)
        #pragma unroll
        for (int j = 0; j < 8; j++) acc[r][j] = 0.f;
    #pragma unroll 8
    for (int k = 0; k < 128; k++) {
        float a[4], bb[8];
        #pragma unroll
        for (int r = 0; r < 4; r++) a[r] = Rs[(ty * 4 + r) * 132 + k];
        #pragma unroll
        for (int j = 0; j < 8; j++) bb[j] = Ws[k * 128 + tx + 16 * j];
        #pragma unroll
        for (int r = 0; r < 4; r++)
            #pragma unroll
            for (int j = 0; j < 8; j++) acc[r][j] = fmaf(a[r], bb[j], acc[r][j]);
    }
    #pragma unroll
    for (int r = 0; r < 4; r++)
        #pragma unroll
        for (int j = 0; j < 8; j++) {
            int rr = m0 + ty * 4 + r, cc = tx + 16 * j;
            g_r2[rr * H_ + cc] = acc[r][j] + brp[cc];
        }
}

// =====================================================================
// Kernel 4: out = r2 @ Wout + bout
// =====================================================================
__global__ void __launch_bounds__(256, 1) out_kernel(
    const float* __restrict__ Wout, const float* __restrict__ bout,
    float* __restrict__ out)
{
    extern __shared__ float smf[];
    float* Rs = smf;
    float* Ws = smf + 64 * 132;
    const int tid = threadIdx.x, ty = tid >> 4, tx = tid & 15;
    const int n0 = blockIdx.x * 128;
    const int m0 = blockIdx.y * 64;

    for (int i = tid; i < 64 * 128; i += 256) {
        int r = i >> 7, c = i & 127;
        Rs[r * 132 + c] = g_r2[(m0 + r) * H_ + c];
    }
    for (int i = tid; i < 128 * 128; i += 256) {
        int k = i >> 7, c = i & 127;
        Ws[i] = Wout[(size_t)k * V_ + n0 + c];
    }
    __syncthreads();

    float acc[4][8];
    #pragma unroll
    for (int r = 0; r < 4; r++)
        #pragma unroll
        for (int j = 0; j < 8; j++) acc[r][j] = 0.f;
    #pragma unroll 8
    for (int k = 0; k < 128; k++) {
        float a[4], bb[8];
        #pragma unroll
        for (int r = 0; r < 4; r++) a[r] = Rs[(ty * 4 + r) * 132 + k];
        #pragma unroll
        for (int j = 0; j < 8; j++) bb[j] = Ws[k * 128 + tx + 16 * j];
        #pragma unroll
        for (int r = 0; r < 4; r++)
            #pragma unroll
            for (int j = 0; j < 8; j++) acc[r][j] = fmaf(a[r], bb[j], acc[r][j]);
    }
    #pragma unroll
    for (int r = 0; r < 4; r++)
        #pragma unroll
        for (int j = 0; j < 8; j++) {
            int rr = m0 + ty * 4 + r, cc = n0 + tx + 16 * j;
            out[(size_t)rr * V_ + cc] = acc[r][j] + bout[cc];
        }
}

// =====================================================================
// launcher
// =====================================================================
extern "C" void kernel_launch(void* const* d_in, const int* in_sizes, int n_in,
                              void* d_out, int out_size)
{
    const int*   seq   = (const int*)  d_in[0];
    const float* embed = (const float*)d_in[1];
    const float* W1    = (const float*)d_in[2];
    const float* b1    = (const float*)d_in[3];
    const float* W2    = (const float*)d_in[4];
    const float* b2    = (const float*)d_in[5];
    const float* gamma = (const float*)d_in[6];
    const float* beta  = (const float*)d_in[7];
    const float* Wrp   = (const float*)d_in[8];
    const float* brp   = (const float*)d_in[9];
    const float* Wout  = (const float*)d_in[10];
    const float* bout  = (const float*)d_in[11];
    float* out = (float*)d_out;

    const int PROJ_SMEM = (64 * 132 + 128 * 128) * 4;

    cudaFuncSetAttribute(encode_mma,   cudaFuncAttributeMaxDynamicSharedMemorySize, ENC_SMEM);
    cudaFuncSetAttribute(rproj_kernel, cudaFuncAttributeMaxDynamicSharedMemorySize, PROJ_SMEM);
    cudaFuncSetAttribute(out_kernel,   cudaFuncAttributeMaxDynamicSharedMemorySize, PROJ_SMEM);

    encode_mma<<<(B_ * L_) / 64, 256, ENC_SMEM>>>(seq, embed, W1, b1, W2, b2, gamma, beta);
    scan_kernel<<<B_, 256>>>();
    rproj_kernel<<<B_ / 64, 256, PROJ_SMEM>>>(Wrp, brp);
    out_kernel<<<dim3(V_ / 128, B_ / 64), 256, PROJ_SMEM>>>(Wout, bout, out);
}